// round 13
// baseline (speedup 1.0000x reference)
#include <cuda_runtime.h>
#include <cuda_fp16.h>
#include <math.h>

// Problem constants
#define R_ 64
#define N_ 512
#define DIM_ 128
#define H_ 8
#define DH_ 64
#define INNER_ 512
#define DPAIR_ 128

// ---------------------------------------------------------------------------
// Device scratch (no allocation allowed)
// ---------------------------------------------------------------------------
__device__ __half g_xh[(size_t)32768 * 128];            // x in fp16
__device__ __half g_WT[(size_t)1664 * 128];             // fused [Wq|Wk|Wv|Wsk]^T, [n][k]
__device__ __half g_WsqT[(size_t)128 * 128];            // Wsq^T [n][k]
__device__ __half g_WoT[(size_t)128 * 512];             // Wo^T [n][k]
__device__ float  g_bias1664[1664];                     // 0...0 | bsk
__device__ __half g_proj[(size_t)32768 * 1664];         // [(r,i)][q|k|v|sk]
__device__ __half g_sqh[(size_t)512 * 128];             // sq
__device__ float  g_w[(size_t)512 * 8 * 64];            // [i][h][r]
__device__ float  g_dots[(size_t)8 * 512 * 512];        // [h][i][j]   (pair bias)
__device__ float  g_dots4[(size_t)4 * 8 * 512 * 512];   // K-split partials
__device__ __half g_Awq[(size_t)8 * 512 * 4096];        // [h][i][(r,d)]  (w-premult q)
__device__ __half g_Bv[(size_t)8 * 4096 * 512];         // [h][(r,d)][j]  (v transposed)
__device__ __half g_attnh[(size_t)8 * 512 * 512];       // softmax(dots) fp16
__device__ __half g_oattnh[(size_t)32768 * 512];        // [(r,i)][h*64+d]

#define DOTS_SLICE ((size_t)8 * 512 * 512)

// ---------------------------------------------------------------------------
// PTX helpers (HMMA path only — tcgen05 is not available: harness PTX target
// is compute_103 (non-'a'), which rejects all arch-specific instructions)
// ---------------------------------------------------------------------------
__device__ __forceinline__ unsigned smaddr(const void* p) {
    return (unsigned)__cvta_generic_to_shared(p);
}
__device__ __forceinline__ void ldsm4(unsigned& r0, unsigned& r1, unsigned& r2,
                                      unsigned& r3, unsigned addr) {
    asm volatile("ldmatrix.sync.aligned.m8n8.x4.shared.b16 {%0,%1,%2,%3},[%4];\n"
                 : "=r"(r0), "=r"(r1), "=r"(r2), "=r"(r3) : "r"(addr));
}
__device__ __forceinline__ void mma16816(float* c, const unsigned* a, const unsigned* b) {
    asm volatile(
        "mma.sync.aligned.m16n8k16.row.col.f32.f16.f16.f32 "
        "{%0,%1,%2,%3},{%4,%5,%6,%7},{%8,%9},{%0,%1,%2,%3};\n"
        : "+f"(c[0]), "+f"(c[1]), "+f"(c[2]), "+f"(c[3])
        : "r"(a[0]), "r"(a[1]), "r"(a[2]), "r"(a[3]), "r"(b[0]), "r"(b[1]));
}
__device__ __forceinline__ void cpa16(void* s, const void* g) {
    asm volatile("cp.async.cg.shared.global [%0],[%1],16;\n"
                 :: "r"(smaddr(s)), "l"(g));
}
__device__ __forceinline__ void cpcommit() { asm volatile("cp.async.commit_group;\n"); }
template <int NN> __device__ __forceinline__ void cpwait() {
    asm volatile("cp.async.wait_group %0;\n" :: "n"(NN));
}

// ---------------------------------------------------------------------------
// Persistent-x projection kernel: [q|k|v|sk] = x @ WT^T + bias
// grid 256 (one CTA per 128 rows), 256 threads.  x tile (128x128) loaded ONCE
// into smem; loop over 13 column blocks of WT (128 rows each) double-buffered.
// Single wave (256 <= 296 slots), 13x fewer x re-reads through L2.
// ---------------------------------------------------------------------------
#define PSK 136    // row stride (halves) for 128-K tiles; conflict-free ldsm
#define PROJ_SMEM (3 * 128 * PSK * 2)   // X + 2 B buffers = 104448 B

__global__ __launch_bounds__(256) void proj_kernel()
{
    extern __shared__ __half ps[];
    __half* Xs = ps;                       // [128][PSK]
    __half* Bs = ps + 128 * PSK;           // [2][128][PSK]

    const int tid = threadIdx.x, warp = tid >> 5, lane = tid & 31;
    const int bm = blockIdx.x * 128;
    const int wm = (warp >> 2) * 64, wn = (warp & 3) * 32;
    const int row2 = tid >> 1, colh = (tid & 1) * 64;

    // load X tile (128 x 128 halves)
    {
        const __half* xp = g_xh + (size_t)(bm + row2) * 128 + colh;
#pragma unroll
        for (int s = 0; s < 8; s++)
            cpa16(&Xs[row2 * PSK + colh + s * 8], xp + s * 8);
    }
    auto loadB = [&](int cb, int buf) {
        const __half* bp = g_WT + (size_t)(cb * 128 + row2) * 128 + colh;
        __half* bs = Bs + buf * (128 * PSK);
#pragma unroll
        for (int s = 0; s < 8; s++)
            cpa16(&bs[row2 * PSK + colh + s * 8], bp + s * 8);
    };
    loadB(0, 0); cpcommit();      // group0 = X + B0
    loadB(1, 1); cpcommit();      // group1 = B1

    for (int cb = 0; cb < 13; cb++) {
        cpwait<1>();
        __syncthreads();

        const unsigned abase = smaddr(Xs);
        const unsigned bbase = smaddr(Bs + (cb & 1) * (128 * PSK));
        float acc[4][4][4];
#pragma unroll
        for (int a = 0; a < 4; a++)
#pragma unroll
            for (int b = 0; b < 4; b++)
#pragma unroll
                for (int c = 0; c < 4; c++) acc[a][b][c] = 0.f;

#pragma unroll
        for (int ks = 0; ks < 8; ++ks) {
            unsigned af[4][4];
#pragma unroll
            for (int tm = 0; tm < 4; tm++) {
                int row = wm + tm * 16 + (lane & 7) + ((lane >> 3) & 1) * 8;
                int col = ks * 16 + (lane >> 4) * 8;
                ldsm4(af[tm][0], af[tm][1], af[tm][2], af[tm][3],
                      abase + (unsigned)(row * PSK + col) * 2u);
            }
            unsigned bf[4][2];
#pragma unroll
            for (int p = 0; p < 2; p++) {
                int row = wn + p * 16 + (lane & 7) + ((lane >> 4) & 1) * 8;
                int col = ks * 16 + ((lane >> 3) & 1) * 8;
                unsigned r0, r1, r2, r3;
                ldsm4(r0, r1, r2, r3, bbase + (unsigned)(row * PSK + col) * 2u);
                bf[2 * p][0] = r0; bf[2 * p][1] = r1;
                bf[2 * p + 1][0] = r2; bf[2 * p + 1][1] = r3;
            }
#pragma unroll
            for (int tm = 0; tm < 4; tm++)
#pragma unroll
                for (int tn = 0; tn < 4; tn++)
                    mma16816(acc[tm][tn], af[tm], bf[tn]);
        }
        __syncthreads();   // all reads of this B buffer done before overwrite
        if (cb + 2 < 13) { loadB(cb + 2, cb & 1); cpcommit(); }

        // epilogue for this column block
        const int bn = cb * 128;
#pragma unroll
        for (int tm = 0; tm < 4; tm++) {
#pragma unroll
            for (int tn = 0; tn < 4; tn++) {
                int row0 = bm + wm + tm * 16 + (lane >> 2);
                int col = bn + wn + tn * 8 + (lane & 3) * 2;
                float b0 = g_bias1664[col], b1 = g_bias1664[col + 1];
#pragma unroll
                for (int half_ : {0, 1}) {
                    int row = row0 + half_ * 8;
                    float v0 = acc[tm][tn][half_ * 2 + 0];
                    float v1 = acc[tm][tn][half_ * 2 + 1];
                    *(__half2*)(g_proj + (size_t)row * 1664 + col) =
                        __floats2half2_rn(v0 + b0, v1 + b1);
                }
            }
        }
    }
}

// ---------------------------------------------------------------------------
// Dots K-split kernel: g_dots4[ks][h][i][j] = 0.125 * sum_{kk in ks-chunk}
//   Awq[h,i,kk] * k[h,j,kk]   where k is read DIRECTLY from g_proj
// grid (jt=4, it=4, z=32: h=z&7, ks=z>>3), K=1024 per z.  Same 3-stage
// cp.async + ldsm/mma machinery as mma_nt; only B addressing differs.
// ---------------------------------------------------------------------------
__global__ __launch_bounds__(256) void dots_kernel()
{
    constexpr int BM = 128, BK = 32, SK = 40;
    extern __shared__ __half sh[];
    __half* Asm = sh;
    __half* Bsm = sh + 3 * BM * SK;

    const int tid = threadIdx.x, warp = tid >> 5, lane = tid & 31;
    const int h = blockIdx.z & 7, ksp = blockIdx.z >> 3;
    const int bn = blockIdx.x * 128;   // j
    const int bm = blockIdx.y * 128;   // i
    const int wm = (warp >> 2) * 64, wn = (warp & 3) * 32;

    const __half* Az = g_Awq + (size_t)h * (512 * 4096) + ksp * 1024;

    float acc[4][4][4];
#pragma unroll
    for (int a = 0; a < 4; a++)
#pragma unroll
        for (int b = 0; b < 4; b++)
#pragma unroll
            for (int c = 0; c < 4; c++) acc[a][b][c] = 0.f;

    const int arow = tid >> 1, acol = (tid & 1) * 16;
    const int nIter = 1024 / BK;   // 32

    auto issue = [&](int it, int buf) {
        const int k0 = it * BK;
        __half* as = Asm + buf * (BM * SK);
        __half* bs = Bsm + buf * (BM * SK);
        const __half* ap = Az + (size_t)(bm + arow) * 4096 + k0 + acol;
        cpa16(&as[arow * SK + acol], ap);
        cpa16(&as[arow * SK + acol + 8], ap + 8);
        // B: k values for row j = bn+arow, absolute k index = ksp*1024+k0+acol
        const int kk = ksp * 1024 + k0 + acol;
        const int r = kk >> 6, dd = kk & 63;
        const __half* bp = g_proj + ((size_t)(r * 512 + bn + arow)) * 1664
                           + 512 + h * 64 + dd;
        cpa16(&bs[arow * SK + acol], bp);
        cpa16(&bs[arow * SK + acol + 8], bp + 8);
    };

    issue(0, 0); cpcommit();
    issue(1, 1); cpcommit();

    for (int it = 0; it < nIter; ++it) {
        cpwait<1>();
        __syncthreads();
        if (it + 2 < nIter) issue(it + 2, (it + 2) % 3);
        cpcommit();

        const int buf = it % 3;
        const unsigned abase = smaddr(Asm + buf * (BM * SK));
        const unsigned bbase = smaddr(Bsm + buf * (BM * SK));
#pragma unroll
        for (int ks = 0; ks < 2; ++ks) {
            unsigned af[4][4];
#pragma unroll
            for (int tm = 0; tm < 4; tm++) {
                int row = wm + tm * 16 + (lane & 7) + ((lane >> 3) & 1) * 8;
                int col = ks * 16 + (lane >> 4) * 8;
                ldsm4(af[tm][0], af[tm][1], af[tm][2], af[tm][3],
                      abase + (unsigned)(row * SK + col) * 2u);
            }
            unsigned bf[4][2];
#pragma unroll
            for (int p = 0; p < 2; p++) {
                int row = wn + p * 16 + (lane & 7) + ((lane >> 4) & 1) * 8;
                int col = ks * 16 + ((lane >> 3) & 1) * 8;
                unsigned r0, r1, r2, r3;
                ldsm4(r0, r1, r2, r3, bbase + (unsigned)(row * SK + col) * 2u);
                bf[2 * p][0] = r0; bf[2 * p][1] = r1;
                bf[2 * p + 1][0] = r2; bf[2 * p + 1][1] = r3;
            }
#pragma unroll
            for (int tm = 0; tm < 4; tm++)
#pragma unroll
                for (int tn = 0; tn < 4; tn++)
                    mma16816(acc[tm][tn], af[tm], bf[tn]);
        }
    }

    float* Cs = g_dots4 + (size_t)(ksp * 8 + h) * (512 * 512);
#pragma unroll
    for (int tm = 0; tm < 4; tm++) {
#pragma unroll
        for (int tn = 0; tn < 4; tn++) {
            int row0 = bm + wm + tm * 16 + (lane >> 2);
            int col = bn + wn + tn * 8 + (lane & 3) * 2;
#pragma unroll
            for (int half_ : {0, 1}) {
                int row = row0 + half_ * 8;
                float2 o = make_float2(0.125f * acc[tm][tn][half_ * 2 + 0],
                                       0.125f * acc[tm][tn][half_ * 2 + 1]);
                *(float2*)(Cs + (size_t)row * 512 + col) = o;
            }
        }
    }
}

// ---------------------------------------------------------------------------
// Generic NT HMMA GEMM:  C(M,N) (+)= A(M,K) @ B(N,K)^T  (K-major fp16)
// OUTM: 1 = Ch = half(acc + bias)   2 = Cf = acc + bias (fp32)
//       4 = attn@v scatter: Ch[((col>>6)*512+row)*512 + z*64 + (col&63)]
// ---------------------------------------------------------------------------
template <int OUTM>
__global__ __launch_bounds__(256) void mma_nt(
    const __half* __restrict__ A, const __half* __restrict__ B,
    float* __restrict__ Cf, __half* __restrict__ Ch,
    const float* __restrict__ bias,
    int K, int ldA, int ldB, int ldC,
    long zsA, long zsB, long zsC)
{
    constexpr int BM = 128, BN = 128, BK = 32, SK = 40;
    constexpr int NT = 4;
    extern __shared__ __half sh[];
    __half* Asm = sh;
    __half* Bsm = sh + 3 * BM * SK;

    const int tid = threadIdx.x, warp = tid >> 5, lane = tid & 31;
    const int z = blockIdx.z;
    const __half* Az = A + (long)z * zsA;
    const __half* Bz = B + (long)z * zsB;
    const long coff = (long)z * zsC;
    const int bm = blockIdx.y * BM, bn = blockIdx.x * BN;
    const int wm = (warp >> 2) * 64, wn = (warp & 3) * 32;

    float acc[4][NT][4];
#pragma unroll
    for (int a = 0; a < 4; a++)
#pragma unroll
        for (int b = 0; b < NT; b++)
#pragma unroll
            for (int c = 0; c < 4; c++) acc[a][b][c] = 0.f;

    const int arow = tid >> 1, acol = (tid & 1) * 16;
    const int nIter = K / BK;

    auto issue = [&](int it, int buf) {
        const int k0 = it * BK;
        __half* as = Asm + buf * (BM * SK);
        __half* bs = Bsm + buf * (BN * SK);
        const __half* ap = Az + (size_t)(bm + arow) * ldA + k0 + acol;
        cpa16(&as[arow * SK + acol], ap);
        cpa16(&as[arow * SK + acol + 8], ap + 8);
        const __half* bp = Bz + (size_t)(bn + arow) * ldB + k0 + acol;
        cpa16(&bs[arow * SK + acol], bp);
        cpa16(&bs[arow * SK + acol + 8], bp + 8);
    };

    issue(0, 0); cpcommit();
    if (nIter > 1) issue(1, 1);
    cpcommit();

    for (int it = 0; it < nIter; ++it) {
        cpwait<1>();
        __syncthreads();
        if (it + 2 < nIter) issue(it + 2, (it + 2) % 3);
        cpcommit();

        const int buf = it % 3;
        const unsigned abase = smaddr(Asm + buf * (BM * SK));
        const unsigned bbase = smaddr(Bsm + buf * (BN * SK));
#pragma unroll
        for (int ks = 0; ks < 2; ++ks) {
            unsigned af[4][4];
#pragma unroll
            for (int tm = 0; tm < 4; tm++) {
                int row = wm + tm * 16 + (lane & 7) + ((lane >> 3) & 1) * 8;
                int col = ks * 16 + (lane >> 4) * 8;
                ldsm4(af[tm][0], af[tm][1], af[tm][2], af[tm][3],
                      abase + (unsigned)(row * SK + col) * 2u);
            }
            unsigned bf[NT][2];
#pragma unroll
            for (int p = 0; p < NT / 2; p++) {
                int row = wn + p * 16 + (lane & 7) + ((lane >> 4) & 1) * 8;
                int col = ks * 16 + ((lane >> 3) & 1) * 8;
                unsigned r0, r1, r2, r3;
                ldsm4(r0, r1, r2, r3, bbase + (unsigned)(row * SK + col) * 2u);
                bf[2 * p][0] = r0; bf[2 * p][1] = r1;
                bf[2 * p + 1][0] = r2; bf[2 * p + 1][1] = r3;
            }
#pragma unroll
            for (int tm = 0; tm < 4; tm++)
#pragma unroll
                for (int tn = 0; tn < NT; tn++)
                    mma16816(acc[tm][tn], af[tm], bf[tn]);
        }
    }

#pragma unroll
    for (int tm = 0; tm < 4; tm++) {
#pragma unroll
        for (int tn = 0; tn < NT; tn++) {
            int row0 = bm + wm + tm * 16 + (lane >> 2);
            int col = bn + wn + tn * 8 + (lane & 3) * 2;
#pragma unroll
            for (int half_ : {0, 1}) {
                int row = row0 + half_ * 8;
                float v0 = acc[tm][tn][half_ * 2 + 0];
                float v1 = acc[tm][tn][half_ * 2 + 1];
                if (OUTM == 1) {
                    float b0 = bias[col], b1 = bias[col + 1];
                    *(__half2*)(Ch + coff + (size_t)row * ldC + col) =
                        __floats2half2_rn(v0 + b0, v1 + b1);
                } else if (OUTM == 2) {
                    float b0 = bias[col], b1 = bias[col + 1];
                    float2 o = make_float2(v0 + b0, v1 + b1);
                    *(float2*)(Cf + coff + (size_t)row * ldC + col) = o;
                } else {
                    size_t addr = ((size_t)((col >> 6) * 512 + row)) * 512
                                  + z * 64 + (col & 63);
                    *(__half2*)(Ch + addr) = __floats2half2_rn(v0, v1);
                }
            }
        }
    }
}

// ---------------------------------------------------------------------------
__global__ __launch_bounds__(256) void cvt_x_kernel(const float* __restrict__ x)
{
    size_t i = (size_t)blockIdx.x * 256 + threadIdx.x;
    float4 v = *(const float4*)(x + i * 4);
    __half2* d = (__half2*)(g_xh + i * 4);
    d[0] = __floats2half2_rn(v.x, v.y);
    d[1] = __floats2half2_rn(v.z, v.w);
}

__global__ __launch_bounds__(256) void build_wb_kernel(
    const float* __restrict__ Wq, const float* __restrict__ Wkv,
    const float* __restrict__ Wsk, const float* __restrict__ Wsq,
    const float* __restrict__ Wo, const float* __restrict__ bsk)
{
    int i = blockIdx.x * 256 + threadIdx.x;
    if (i < 1664 * 128) {
        int n = i >> 7, k = i & 127;
        float v;
        if (n < 512) v = Wq[k * 512 + n];
        else if (n < 1536) v = Wkv[k * 1024 + (n - 512)];
        else v = Wsk[k * 128 + (n - 1536)];
        g_WT[(size_t)n * 128 + k] = __float2half(v);
    }
    if (i < 128 * 128) {
        int n = i >> 7, k = i & 127;
        g_WsqT[(size_t)n * 128 + k] = __float2half(Wsq[k * 128 + n]);
    }
    if (i < 128 * 512) {
        int n = i >> 9, k = i & 511;
        g_WoT[(size_t)n * 512 + k] = __float2half(Wo[k * 128 + n]);
    }
    if (i < 1664) g_bias1664[i] = (i < 1536) ? 0.f : bsk[i - 1536];
}

__global__ __launch_bounds__(256) void wsoft_kernel()
{
    const int g = threadIdx.x >> 6, r = threadIdx.x & 63;
    const int ih = blockIdx.x * 4 + g;
    const int i = ih >> 3, h = ih & 7;
    __shared__ float sm[4][64];
    const __half* sqv = g_sqh + (size_t)i * 128 + h * 16;
    const __half* skv = g_proj + ((size_t)(r * 512 + i)) * 1664 + 1536 + h * 16;
    float dot = 0.f;
#pragma unroll
    for (int d = 0; d < 16; d++)
        dot += __half2float(sqv[d]) * __half2float(skv[d]);
    float logit = dot * 0.25f;
    sm[g][r] = logit;
    __syncthreads();
    float mx = -1e30f;
#pragma unroll 8
    for (int t = 0; t < 64; t++) mx = fmaxf(mx, sm[g][t]);
    __syncthreads();
    float e = __expf(logit - mx);
    sm[g][r] = e;
    __syncthreads();
    float sum = 0.f;
#pragma unroll 8
    for (int t = 0; t < 64; t++) sum += sm[g][t];
    g_w[(size_t)ih * 64 + r] = e / sum;
}

// Build dots A operand only: A = w*q -> [h][i][(r,d)]  (k read direct now)
__global__ __launch_bounds__(256) void prep_ab_kernel()
{
    unsigned u = blockIdx.x * 256 + threadIdx.x;
    int dseg = u & 7;
    int r = (u >> 3) & 63;
    int i = (u >> 9) & 511;
    int h = u >> 18;
    size_t src = ((size_t)(r * 512 + i)) * 1664 + h * 64 + dseg * 8;
    uint4 qv = *(const uint4*)(g_proj + src);
    float w = g_w[((size_t)i * 8 + h) * 64 + r];
    __half2* hp = (__half2*)&qv;
#pragma unroll
    for (int t = 0; t < 4; t++) {
        float2 f = __half22float2(hp[t]);
        hp[t] = __floats2half2_rn(f.x * w, f.y * w);
    }
    size_t dst = ((size_t)(h * 512 + i)) * 4096 + r * 64 + dseg * 8;
    *(uint4*)(g_Awq + dst) = qv;
}

__global__ __launch_bounds__(256) void vtrans_kernel()
{
    const int jt = blockIdx.x, z = blockIdx.y;
    const int r = z >> 3, h = z & 7;
    __shared__ __half ts[128][72];
    const int tid = threadIdx.x;
#pragma unroll
    for (int p = 0; p < 4; p++) {
        int u = tid + p * 256;
        int j = u >> 3, dseg = u & 7;
        uint4 v = *(const uint4*)(g_proj +
            ((size_t)(r * 512 + jt * 128 + j)) * 1664 + 1024 + h * 64 + dseg * 8);
        *(uint4*)&ts[j][dseg * 8] = v;
    }
    __syncthreads();
#pragma unroll
    for (int p = 0; p < 4; p++) {
        int u = tid + p * 256;
        int d = u & 63, jseg = u >> 6;
        __half tmp[8];
#pragma unroll
        for (int jj = 0; jj < 8; jj++) tmp[jj] = ts[jseg * 8 + jj][d];
        *(uint4*)(g_Bv + (size_t)h * (4096 * 512)
                  + ((size_t)(r * 64 + d)) * 512 + jt * 128 + jseg * 8) =
            *(uint4*)tmp;
    }
}

__global__ __launch_bounds__(256) void pb_kernel(
    const float* __restrict__ pair, const float* __restrict__ ln_g,
    const float* __restrict__ ln_b, const float* __restrict__ Wpair)
{
    const int i = blockIdx.x;
    const int warp = threadIdx.x >> 5;
    const int lane = threadIdx.x & 31;
    const int j = blockIdx.y * 8 + warp;
    const float* p = pair + ((size_t)i * 512 + j) * 128;
    float xv[4];
#pragma unroll
    for (int t = 0; t < 4; t++) xv[t] = p[lane + 32 * t];
    float s  = xv[0] + xv[1] + xv[2] + xv[3];
    float s2 = xv[0]*xv[0] + xv[1]*xv[1] + xv[2]*xv[2] + xv[3]*xv[3];
#pragma unroll
    for (int o = 16; o > 0; o >>= 1) {
        s  += __shfl_xor_sync(0xffffffffu, s,  o);
        s2 += __shfl_xor_sync(0xffffffffu, s2, o);
    }
    const float mu  = s * (1.f / 128.f);
    const float var = s2 * (1.f / 128.f) - mu * mu;
    const float inv = rsqrtf(var + 1e-5f);
    float y[4];
#pragma unroll
    for (int t = 0; t < 4; t++) {
        int c = lane + 32 * t;
        y[t] = (xv[t] - mu) * inv * ln_g[c] + ln_b[c];
    }
    float accs[8];
#pragma unroll
    for (int h = 0; h < 8; h++) {
        float a = 0.f;
#pragma unroll
        for (int t = 0; t < 4; t++) {
            int c = lane + 32 * t;
            a += y[t] * Wpair[c * 8 + h];
        }
#pragma unroll
        for (int o = 16; o > 0; o >>= 1) a += __shfl_xor_sync(0xffffffffu, a, o);
        accs[h] = a;
    }
    if (lane < 8)
        g_dots[((size_t)lane * 512 + i) * 512 + j] = accs[lane];
}

__global__ __launch_bounds__(256) void softj_kernel()
{
    const size_t off = (size_t)blockIdx.x * 512;
    __half* orow = g_attnh + off;
    __shared__ float red[256];
    const int t = threadIdx.x;
    float v0 = g_dots[off + t] + g_dots4[off + t]
             + g_dots4[DOTS_SLICE + off + t]
             + g_dots4[2 * DOTS_SLICE + off + t]
             + g_dots4[3 * DOTS_SLICE + off + t];
    float v1 = g_dots[off + t + 256] + g_dots4[off + t + 256]
             + g_dots4[DOTS_SLICE + off + t + 256]
             + g_dots4[2 * DOTS_SLICE + off + t + 256]
             + g_dots4[3 * DOTS_SLICE + off + t + 256];
    red[t] = fmaxf(v0, v1);
    __syncthreads();
#pragma unroll
    for (int o = 128; o > 0; o >>= 1) {
        if (t < o) red[t] = fmaxf(red[t], red[t + o]);
        __syncthreads();
    }
    const float mx = red[0];
    __syncthreads();
    float e0 = __expf(v0 - mx), e1 = __expf(v1 - mx);
    red[t] = e0 + e1;
    __syncthreads();
#pragma unroll
    for (int o = 128; o > 0; o >>= 1) {
        if (t < o) red[t] = red[t] + red[t + o];
        __syncthreads();
    }
    const float inv = 1.f / red[0];
    orow[t] = __float2half(e0 * inv);
    orow[t + 256] = __float2half(e1 * inv);
}

// ---------------------------------------------------------------------------
extern "C" void kernel_launch(void* const* d_in, const int* in_sizes, int n_in,
                              void* d_out, int out_size)
{
    const float* x     = (const float*)d_in[0];
    const float* pair  = (const float*)d_in[1];
    const float* Wq    = (const float*)d_in[2];
    const float* Wkv   = (const float*)d_in[3];
    const float* Wo    = (const float*)d_in[4];
    const float* bo    = (const float*)d_in[5];
    const float* ln_g  = (const float*)d_in[6];
    const float* ln_b  = (const float*)d_in[7];
    const float* Wpair = (const float*)d_in[8];
    const float* Wsq   = (const float*)d_in[9];
    const float* bsq   = (const float*)d_in[10];
    const float* Wsk   = (const float*)d_in[11];
    const float* bsk   = (const float*)d_in[12];
    float* out = (float*)d_out;

    __half *p_xh, *p_WsqT, *p_WoT, *p_sqh, *p_attnh, *p_oattnh, *p_Bv;
    cudaGetSymbolAddress((void**)&p_xh, g_xh);
    cudaGetSymbolAddress((void**)&p_WsqT, g_WsqT);
    cudaGetSymbolAddress((void**)&p_WoT, g_WoT);
    cudaGetSymbolAddress((void**)&p_sqh, g_sqh);
    cudaGetSymbolAddress((void**)&p_attnh, g_attnh);
    cudaGetSymbolAddress((void**)&p_oattnh, g_oattnh);
    cudaGetSymbolAddress((void**)&p_Bv, g_Bv);

    const int SMEM = 3 * (128 + 128) * 40 * 2;   // 61440 B
    cudaFuncSetAttribute(mma_nt<1>, cudaFuncAttributeMaxDynamicSharedMemorySize, SMEM);
    cudaFuncSetAttribute(mma_nt<2>, cudaFuncAttributeMaxDynamicSharedMemorySize, SMEM);
    cudaFuncSetAttribute(mma_nt<4>, cudaFuncAttributeMaxDynamicSharedMemorySize, SMEM);
    cudaFuncSetAttribute(dots_kernel, cudaFuncAttributeMaxDynamicSharedMemorySize, SMEM);
    cudaFuncSetAttribute(proj_kernel, cudaFuncAttributeMaxDynamicSharedMemorySize,
                         PROJ_SMEM);

    // prep
    build_wb_kernel<<<832, 256>>>(Wq, Wkv, Wsk, Wsq, Wo, bsk);
    cvt_x_kernel<<<4096, 256>>>(x);
    // pair bias (fp32) -> g_dots
    pb_kernel<<<dim3(512, 64), 256>>>(pair, ln_g, ln_b, Wpair);
    // fused projection: persistent-x, single wave
    proj_kernel<<<256, 256, PROJ_SMEM>>>();
    // sq = x[:512] @ Wsq^T + bsq
    mma_nt<1><<<dim3(1, 4, 1), 256, SMEM>>>(
        p_xh, p_WsqT, nullptr, p_sqh, bsq, 128, 128, 128, 128, 0, 0, 0);
    // tied-row softmax weights
    wsoft_kernel<<<1024, 256>>>();
    // dots A operand (w*q scatter only; k read direct by dots_kernel)
    prep_ab_kernel<<<8192, 256>>>();
    // v transpose -> [h][(r,d)][j]
    vtrans_kernel<<<dim3(4, 512), 256>>>();
    // dots partials: 0.125 * (wq) @ k^T per (h, ksplit), k direct from g_proj
    dots_kernel<<<dim3(4, 4, 32), 256, SMEM>>>();
    // softmax over j (sums partials) -> fp16 attn
    softj_kernel<<<4096, 256>>>();
    // out_attn = attn @ v per h: M=512, N=4096, K=512, Z=8, scatter epilogue
    mma_nt<4><<<dim3(32, 4, 8), 256, SMEM>>>(
        p_attnh, p_Bv, nullptr, p_oattnh, nullptr, 512, 512, 512, 0,
        (long)512 * 512, (long)4096 * 512, 0);
    // final: out = oattn @ Wo^T + bo  (M=32768, N=128, K=512)
    mma_nt<2><<<dim3(1, 256, 1), 256, SMEM>>>(
        p_oattnh, p_WoT, out, nullptr, bo, 512, 512, 512, 128, 0, 0, 0);
}